// round 1
// baseline (speedup 1.0000x reference)
#include <cuda_runtime.h>
#include <cstdint>

#define CC 64
#define HWN 262144
#define NB 256
#define FINE 32768
#define CAP 48

// ---------------- scratch (static device globals; re-initialized every launch) ----
__device__ int    g_nI, g_nJ;
__device__ int    g_minJ[CC];            // float bits (non-negative -> int-order == float-order)
__device__ int    g_maxJ[CC];
__device__ int    g_histJ[CC * NB];
__device__ float  g_hisJf[CC * NB];
__device__ float  g_cumJ[CC * NB];
__device__ float  g_minJf[CC];
__device__ float  g_stepf[CC];
__device__ int    g_cnt[CC * FINE];
__device__ int    g_off[CC * (FINE + 1)];
__device__ int    g_cur[CC * FINE];
__device__ float  g_buf[CC * HWN];
__device__ double g_loss;

// ---------------- K0: zero/init all per-launch state ------------------------------
__global__ void k_init() {
    int i = blockIdx.x * blockDim.x + threadIdx.x;
    if (i < CC * FINE) g_cnt[i] = 0;
    if (i < CC * NB)   g_histJ[i] = 0;
    if (i < CC) { g_minJ[i] = 0x7F800000; g_maxJ[i] = 0; }
    if (i == 0) { g_nI = 0; g_nJ = 0; g_loss = 0.0; }
}

// ---------------- K1: nI, nJ -------------------------------------------------------
__global__ void k_masksum(const int4* __restrict__ mI, const int4* __restrict__ mJ) {
    int i = blockIdx.x * blockDim.x + threadIdx.x;       // HWN/4 threads
    int4 a = mI[i], b = mJ[i];
    int sI = a.x + a.y + a.z + a.w;
    int sJ = b.x + b.y + b.z + b.w;
    for (int o = 16; o; o >>= 1) {
        sI += __shfl_down_sync(0xFFFFFFFFu, sI, o);
        sJ += __shfl_down_sync(0xFFFFFFFFu, sJ, o);
    }
    if ((threadIdx.x & 31) == 0) { atomicAdd(&g_nI, sI); atomicAdd(&g_nJ, sJ); }
}

// ---------------- K2: per-channel masked min/max of J -----------------------------
__global__ void k_minmax(const float4* __restrict__ J, const int4* __restrict__ mJ) {
    int c = blockIdx.y;
    int i = blockIdx.x * blockDim.x + threadIdx.x;       // HWN/4 per channel
    float4 v = J[c * (HWN / 4) + i];
    int4  m = mJ[i];
    float mn = 1e30f, mx = -1e30f;
    if (m.x) { mn = fminf(mn, v.x); mx = fmaxf(mx, v.x); }
    if (m.y) { mn = fminf(mn, v.y); mx = fmaxf(mx, v.y); }
    if (m.z) { mn = fminf(mn, v.z); mx = fmaxf(mx, v.z); }
    if (m.w) { mn = fminf(mn, v.w); mx = fmaxf(mx, v.w); }
    for (int o = 16; o; o >>= 1) {
        mn = fminf(mn, __shfl_down_sync(0xFFFFFFFFu, mn, o));
        mx = fmaxf(mx, __shfl_down_sync(0xFFFFFFFFu, mx, o));
    }
    __shared__ float smn[8], smx[8];
    int t = threadIdx.x;
    if ((t & 31) == 0) { smn[t >> 5] = mn; smx[t >> 5] = mx; }
    __syncthreads();
    if (t < 8) {
        mn = smn[t]; mx = smx[t];
        for (int o = 4; o; o >>= 1) {
            mn = fminf(mn, __shfl_down_sync(0xFFu, mn, o));
            mx = fmaxf(mx, __shfl_down_sync(0xFFu, mx, o));
        }
        if (t == 0) {
            if (mn < 1e30f)  atomicMin(&g_minJ[c], __float_as_int(mn));
            if (mx > -1e30f) atomicMax(&g_maxJ[c], __float_as_int(mx));
        }
    }
}

// ---------------- K3: 256-bin masked histogram of J -------------------------------
__global__ void k_histJ(const float4* __restrict__ J, const int4* __restrict__ mJ) {
    __shared__ int sh[NB];
    int c = blockIdx.y;
    int t = threadIdx.x;
    sh[t] = 0;                 // blockDim == NB == 256
    __syncthreads();
    float minf = __int_as_float(g_minJ[c]);
    float maxf = __int_as_float(g_maxJ[c]);
    float step = (maxf - minf) * (1.0f / NB);
    float sden = fmaxf(step, 1e-12f);
    int i = blockIdx.x * blockDim.x + t;
    float4 v = J[c * (HWN / 4) + i];
    int4  m = mJ[i];
    if (m.x) { int b = (int)floorf((v.x - minf) / sden); b = max(0, min(NB - 1, b)); atomicAdd(&sh[b], 1); }
    if (m.y) { int b = (int)floorf((v.y - minf) / sden); b = max(0, min(NB - 1, b)); atomicAdd(&sh[b], 1); }
    if (m.z) { int b = (int)floorf((v.z - minf) / sden); b = max(0, min(NB - 1, b)); atomicAdd(&sh[b], 1); }
    if (m.w) { int b = (int)floorf((v.w - minf) / sden); b = max(0, min(NB - 1, b)); atomicAdd(&sh[b], 1); }
    __syncthreads();
    if (sh[t]) atomicAdd(&g_histJ[c * NB + t], sh[t]);
}

// ---------------- K4: scale by nI/nJ, sequential f32 cumsum ------------------------
__global__ void k_prep() {
    int c = blockIdx.x, t = threadIdx.x;
    float minf = __int_as_float(g_minJ[c]);
    float maxf = __int_as_float(g_maxJ[c]);
    float step = (maxf - minf) * (1.0f / NB);
    if (t == 0) { g_minJf[c] = minf; g_stepf[c] = step; }
    float scale = (float)g_nI / (float)g_nJ;
    g_hisJf[c * NB + t] = (float)g_histJ[c * NB + t] * scale;
    __syncthreads();
    if (t == 0) {
        float run = 0.0f;
        for (int b = 0; b < NB; b++) { run += g_hisJf[c * NB + b]; g_cumJ[c * NB + b] = run; }
    }
}

// ---------------- K5: fine (32768-bin) histogram of masked I -----------------------
__global__ void k_fhist(const float4* __restrict__ I, const int4* __restrict__ mI) {
    int c = blockIdx.y;
    int i = blockIdx.x * blockDim.x + threadIdx.x;
    float4 v = I[c * (HWN / 4) + i];
    int4  m = mI[i];
    if (m.x) { int b = min((int)(v.x * (float)FINE), FINE - 1); atomicAdd(&g_cnt[c * FINE + b], 1); }
    if (m.y) { int b = min((int)(v.y * (float)FINE), FINE - 1); atomicAdd(&g_cnt[c * FINE + b], 1); }
    if (m.z) { int b = min((int)(v.z * (float)FINE), FINE - 1); atomicAdd(&g_cnt[c * FINE + b], 1); }
    if (m.w) { int b = min((int)(v.w * (float)FINE), FINE - 1); atomicAdd(&g_cnt[c * FINE + b], 1); }
}

// ---------------- K6: per-channel exclusive scan of bucket counts ------------------
__global__ void k_scan() {
    int c = blockIdx.x, t = threadIdx.x;                 // 1024 threads
    __shared__ int sh[1024];
    __shared__ int carry;
    if (t == 0) carry = 0;
    __syncthreads();
    for (int tile = 0; tile < FINE / 1024; tile++) {
        int idx = c * FINE + tile * 1024 + t;
        int x = g_cnt[idx];
        sh[t] = x; __syncthreads();
        for (int o = 1; o < 1024; o <<= 1) {
            int v = (t >= o) ? sh[t - o] : 0;
            __syncthreads();
            sh[t] += v;
            __syncthreads();
        }
        int incl = sh[t];
        int cold = carry;
        int excl = cold + incl - x;
        g_off[c * (FINE + 1) + tile * 1024 + t] = excl;
        g_cur[idx] = excl;
        __syncthreads();
        if (t == 1023) carry = cold + incl;
        __syncthreads();
    }
    if (t == 0) g_off[c * (FINE + 1) + FINE] = carry;
}

// ---------------- K7: scatter masked I values into buckets -------------------------
__global__ void k_scatter(const float4* __restrict__ I, const int4* __restrict__ mI) {
    int c = blockIdx.y;
    int i = blockIdx.x * blockDim.x + threadIdx.x;
    float4 v = I[c * (HWN / 4) + i];
    int4  m = mI[i];
    if (m.x) { int b = min((int)(v.x * (float)FINE), FINE - 1); int p = atomicAdd(&g_cur[c * FINE + b], 1); g_buf[c * HWN + p] = v.x; }
    if (m.y) { int b = min((int)(v.y * (float)FINE), FINE - 1); int p = atomicAdd(&g_cur[c * FINE + b], 1); g_buf[c * HWN + p] = v.y; }
    if (m.z) { int b = min((int)(v.z * (float)FINE), FINE - 1); int p = atomicAdd(&g_cur[c * FINE + b], 1); g_buf[c * HWN + p] = v.z; }
    if (m.w) { int b = min((int)(v.w * (float)FINE), FINE - 1); int p = atomicAdd(&g_cur[c * FINE + b], 1); g_buf[c * HWN + p] = v.w; }
}

// ---------------- K8: per-bucket sort + CDF-inverse remap + squared-error reduce ---
__global__ void k_loss() {
    int c = blockIdx.y;
    int t = threadIdx.x;                                 // 256 threads, 1 bucket/thread
    __shared__ float scum[NB], shis[NB];
    scum[t] = g_cumJ[c * NB + t];
    shis[t] = g_hisJf[c * NB + t];
    __syncthreads();
    float minf = g_minJf[c], step = g_stepf[c];
    int b = blockIdx.x * blockDim.x + t;
    int s = g_off[c * (FINE + 1) + b];
    int e = g_off[c * (FINE + 1) + b + 1];
    int m = e - s; if (m > CAP) m = CAP;

    float v[CAP];
    for (int i = 0; i < m; i++) {                        // insertion sort (avg ~4 items)
        float x = g_buf[c * HWN + s + i];
        int j = i;
        while (j > 0 && v[j - 1] > x) { v[j] = v[j - 1]; j--; }
        v[j] = x;
    }

    double acc = 0.0;
    for (int i = 0; i < m; i++) {
        float r = (float)(s + i + 1);                    // 1-indexed rank among masked
        int pos = 0;                                     // lower_bound(scum, r)
        #pragma unroll
        for (int st = 128; st > 0; st >>= 1) {
            int np = pos + st;
            if (np <= NB && scum[np - 1] < r) pos = np;
        }
        int bi = pos > NB - 1 ? NB - 1 : pos;
        float cb = scum[bi], hb = shis[bi];
        float lo = cb - hb;
        float ratio = (r - lo) / fmaxf(hb, 1e-12f);
        ratio = fminf(fmaxf(ratio, 0.0f), 1.0f);
        float f = minf + ((float)bi + ratio) * step;
        float d = v[i] - f;
        acc += (double)d * (double)d;
    }

    for (int o = 16; o; o >>= 1) acc += __shfl_down_sync(0xFFFFFFFFu, acc, o);
    __shared__ double sacc[8];
    if ((t & 31) == 0) sacc[t >> 5] = acc;
    __syncthreads();
    if (t < 8) {
        double a = sacc[t];
        for (int o = 4; o; o >>= 1) a += __shfl_down_sync(0xFFu, a, o);
        if (t == 0) atomicAdd(&g_loss, a);
    }
}

// ---------------- K9: finalize ------------------------------------------------------
__global__ void k_final(float* __restrict__ out) {
    out[0] = (float)(g_loss * (100.0 / ((double)CC * (double)HWN)));
}

extern "C" void kernel_launch(void* const* d_in, const int* in_sizes, int n_in,
                              void* d_out, int out_size) {
    const float* I = (const float*)d_in[0];
    const float* J = (const float*)d_in[1];
    const int*  mI = (const int*)d_in[2];
    const int*  mJ = (const int*)d_in[3];
    float* out = (float*)d_out;

    k_init<<<(CC * FINE + 1023) / 1024, 1024>>>();
    k_masksum<<<(HWN / 4) / 256, 256>>>((const int4*)mI, (const int4*)mJ);

    dim3 g((HWN / 4) / 256, CC);
    k_minmax<<<g, 256>>>((const float4*)J, (const int4*)mJ);
    k_histJ<<<g, 256>>>((const float4*)J, (const int4*)mJ);
    k_prep<<<CC, 256>>>();
    k_fhist<<<g, 256>>>((const float4*)I, (const int4*)mI);
    k_scan<<<CC, 1024>>>();
    k_scatter<<<g, 256>>>((const float4*)I, (const int4*)mI);

    dim3 g2(FINE / 256, CC);
    k_loss<<<g2, 256>>>();
    k_final<<<1, 1>>>(out);
}

// round 2
// speedup vs baseline: 1.0495x; 1.0495x over previous
#include <cuda_runtime.h>
#include <cstdint>

#define CC 64
#define HWN 262144
#define NB 256
#define FINE 32768
#define TILE 1024
#define NTILE (FINE / TILE)   // 32
#define SLAB 16

// ---------------- scratch ----------------------------------------------------------
__device__ int    g_nI, g_nJ;
__device__ int    g_minJ[CC];           // float bits (values >= 0 -> int order == float order)
__device__ int    g_maxJ[CC];
__device__ int    g_histJ[CC * NB];
__device__ float  g_hisJf[CC * NB];
__device__ float  g_cumJ[CC * NB];
__device__ float  g_minJf[CC];
__device__ float  g_stepf[CC];
__device__ int    g_cnt[CC * FINE];
__device__ int    g_off[CC * (FINE + 1)];
__device__ int    g_cur[CC * FINE];
__device__ int    g_tile[CC * NTILE];
__device__ float  g_buf[CC * HWN];
__device__ double g_loss;

static __device__ __forceinline__ int fbin(float x) {
    int b = (int)(x * (float)FINE);
    return b < 0 ? 0 : (b > FINE - 1 ? FINE - 1 : b);
}

// ---------------- K0: init ----------------------------------------------------------
__global__ void k_init() {
    int i = blockIdx.x * blockDim.x + threadIdx.x;
    if (i < CC * FINE) g_cnt[i] = 0;
    if (i < CC * NB)   g_histJ[i] = 0;
    if (i < CC) { g_minJ[i] = 0x7F800000; g_maxJ[i] = 0; }
    if (i == 0) { g_nI = 0; g_nJ = 0; g_loss = 0.0; }
}

// ---------------- K1: fused minmax(J) + fine-hist(I) + mask sums --------------------
__global__ void k_pass1(const float4* __restrict__ I, const float4* __restrict__ J,
                        const int4* __restrict__ mI4, const int4* __restrict__ mJ4) {
    int c = blockIdx.y;
    int i = blockIdx.x * blockDim.x + threadIdx.x;     // HWN/8 per channel
    int base = c * (HWN / 4) + i * 2;

    float4 j0 = J[base], j1 = J[base + 1];
    int4  mj0 = mJ4[i * 2], mj1 = mJ4[i * 2 + 1];
    float4 i0 = I[base], i1 = I[base + 1];
    int4  mi0 = mI4[i * 2], mi1 = mI4[i * 2 + 1];

    // --- masked min/max of J ---
    float mn = 1e30f, mx = -1e30f;
    if (mj0.x) { mn = fminf(mn, j0.x); mx = fmaxf(mx, j0.x); }
    if (mj0.y) { mn = fminf(mn, j0.y); mx = fmaxf(mx, j0.y); }
    if (mj0.z) { mn = fminf(mn, j0.z); mx = fmaxf(mx, j0.z); }
    if (mj0.w) { mn = fminf(mn, j0.w); mx = fmaxf(mx, j0.w); }
    if (mj1.x) { mn = fminf(mn, j1.x); mx = fmaxf(mx, j1.x); }
    if (mj1.y) { mn = fminf(mn, j1.y); mx = fmaxf(mx, j1.y); }
    if (mj1.z) { mn = fminf(mn, j1.z); mx = fmaxf(mx, j1.z); }
    if (mj1.w) { mn = fminf(mn, j1.w); mx = fmaxf(mx, j1.w); }

    // --- fine histogram of masked I (global spread atomics) ---
    int* cnt = g_cnt + c * FINE;
    if (mi0.x) atomicAdd(&cnt[fbin(i0.x)], 1);
    if (mi0.y) atomicAdd(&cnt[fbin(i0.y)], 1);
    if (mi0.z) atomicAdd(&cnt[fbin(i0.z)], 1);
    if (mi0.w) atomicAdd(&cnt[fbin(i0.w)], 1);
    if (mi1.x) atomicAdd(&cnt[fbin(i1.x)], 1);
    if (mi1.y) atomicAdd(&cnt[fbin(i1.y)], 1);
    if (mi1.z) atomicAdd(&cnt[fbin(i1.z)], 1);
    if (mi1.w) atomicAdd(&cnt[fbin(i1.w)], 1);

    // --- mask sums (channel 0 only) ---
    if (c == 0) {
        int sI = mi0.x + mi0.y + mi0.z + mi0.w + mi1.x + mi1.y + mi1.z + mi1.w;
        int sJ = mj0.x + mj0.y + mj0.z + mj0.w + mj1.x + mj1.y + mj1.z + mj1.w;
        for (int o = 16; o; o >>= 1) {
            sI += __shfl_down_sync(0xFFFFFFFFu, sI, o);
            sJ += __shfl_down_sync(0xFFFFFFFFu, sJ, o);
        }
        if ((threadIdx.x & 31) == 0) { atomicAdd(&g_nI, sI); atomicAdd(&g_nJ, sJ); }
    }

    // --- block reduce min/max ---
    for (int o = 16; o; o >>= 1) {
        mn = fminf(mn, __shfl_down_sync(0xFFFFFFFFu, mn, o));
        mx = fmaxf(mx, __shfl_down_sync(0xFFFFFFFFu, mx, o));
    }
    __shared__ float smn[8], smx[8];
    int t = threadIdx.x;
    if ((t & 31) == 0) { smn[t >> 5] = mn; smx[t >> 5] = mx; }
    __syncthreads();
    if (t < 8) {
        mn = smn[t]; mx = smx[t];
        for (int o = 4; o; o >>= 1) {
            mn = fminf(mn, __shfl_down_sync(0xFFu, mn, o));
            mx = fmaxf(mx, __shfl_down_sync(0xFFu, mx, o));
        }
        if (t == 0) {
            if (mn < 1e30f)  atomicMin(&g_minJ[c], __float_as_int(mn));
            if (mx > -1e30f) atomicMax(&g_maxJ[c], __float_as_int(mx));
        }
    }
}

// ---------------- K2: 256-bin masked histogram of J (2-replica shared) --------------
__global__ void k_histJ(const float4* __restrict__ J, const int4* __restrict__ mJ4) {
    __shared__ int sh[2 * NB];
    int c = blockIdx.y;
    int t = threadIdx.x;
    sh[t] = 0; sh[t + NB] = 0;
    __syncthreads();
    float minf = __int_as_float(g_minJ[c]);
    float maxf = __int_as_float(g_maxJ[c]);
    float step = (maxf - minf) * (1.0f / NB);
    float sden = fmaxf(step, 1e-12f);
    int i = blockIdx.x * blockDim.x + t;
    int base = c * (HWN / 4) + i * 2;
    float4 v0 = J[base], v1 = J[base + 1];
    int4  m0 = mJ4[i * 2], m1 = mJ4[i * 2 + 1];
    int* h = sh + (t & 1) * NB;
    #define HADD(mm, vv) if (mm) { int b = (int)floorf((vv - minf) / sden); b = max(0, min(NB - 1, b)); atomicAdd(&h[b], 1); }
    HADD(m0.x, v0.x) HADD(m0.y, v0.y) HADD(m0.z, v0.z) HADD(m0.w, v0.w)
    HADD(m1.x, v1.x) HADD(m1.y, v1.y) HADD(m1.z, v1.z) HADD(m1.w, v1.w)
    #undef HADD
    __syncthreads();
    int s = sh[t] + sh[t + NB];
    if (s) atomicAdd(&g_histJ[c * NB + t], s);
}

// ---------------- K3a: per-tile local scan ------------------------------------------
__global__ void k_scanA() {
    int c = blockIdx.y, tile = blockIdx.x, t = threadIdx.x;
    __shared__ int sh[TILE];
    int idx = c * FINE + tile * TILE + t;
    int x = g_cnt[idx];
    sh[t] = x;
    __syncthreads();
    for (int o = 1; o < TILE; o <<= 1) {
        int v = (t >= o) ? sh[t - o] : 0;
        __syncthreads();
        sh[t] += v;
        __syncthreads();
    }
    int incl = sh[t];
    g_off[c * (FINE + 1) + tile * TILE + t] = incl - x;  // tile-local exclusive
    if (t == TILE - 1) g_tile[c * NTILE + tile] = incl;
}

// ---------------- K3b: tile-sum scan + CDF prep -------------------------------------
__global__ void k_scanB() {
    int c = blockIdx.x, t = threadIdx.x;   // 256 threads
    if (t < 32) {
        int v = g_tile[c * NTILE + t];
        int incl = v;
        for (int o = 1; o < 32; o <<= 1) {
            int u = __shfl_up_sync(0xFFFFFFFFu, incl, o);
            if (t >= o) incl += u;
        }
        g_tile[c * NTILE + t] = incl - v;                 // exclusive
        if (t == 31) g_off[c * (FINE + 1) + FINE] = incl; // channel total
    }
    float minf = __int_as_float(g_minJ[c]);
    float maxf = __int_as_float(g_maxJ[c]);
    float step = (maxf - minf) * (1.0f / NB);
    if (t == 0) { g_minJf[c] = minf; g_stepf[c] = step; }
    float scale = (float)g_nI / (float)g_nJ;
    g_hisJf[c * NB + t] = (float)g_histJ[c * NB + t] * scale;
    __syncthreads();
    if (t == 0) {
        float run = 0.0f;
        for (int b = 0; b < NB; b++) { run += g_hisJf[c * NB + b]; g_cumJ[c * NB + b] = run; }
    }
}

// ---------------- K3c: add tile offsets ---------------------------------------------
__global__ void k_scanC() {
    int c = blockIdx.y, tile = blockIdx.x, t = threadIdx.x;
    int add = g_tile[c * NTILE + tile];
    int i = c * (FINE + 1) + tile * TILE + t;
    int v = g_off[i] + add;
    g_off[i] = v;
    g_cur[c * FINE + tile * TILE + t] = v;
}

// ---------------- K4: scatter masked I into buckets ----------------------------------
__global__ void k_scatter(const float4* __restrict__ I, const int4* __restrict__ mI4) {
    int c = blockIdx.y;
    int i = blockIdx.x * blockDim.x + threadIdx.x;
    int base = c * (HWN / 4) + i * 2;
    float4 v0 = I[base], v1 = I[base + 1];
    int4  m0 = mI4[i * 2], m1 = mI4[i * 2 + 1];
    int* cur = g_cur + c * FINE;
    float* buf = g_buf + c * HWN;
    #define SC(mm, vv) if (mm) { int p = atomicAdd(&cur[fbin(vv)], 1); buf[p] = vv; }
    SC(m0.x, v0.x) SC(m0.y, v0.y) SC(m0.z, v0.z) SC(m0.w, v0.w)
    SC(m1.x, v1.x) SC(m1.y, v1.y) SC(m1.z, v1.z) SC(m1.w, v1.w)
    #undef SC
}

// ---------------- K5: per-bucket rank-count + CDF-inverse + loss ---------------------
__global__ void k_loss() {
    int c = blockIdx.y;
    int t = threadIdx.x;                                 // 256 threads, 1 bucket/thread
    __shared__ float scum[NB], shis[NB];
    __shared__ float slab[SLAB * 256];                   // column t -> bank t%32, conflict-free
    scum[t] = g_cumJ[c * NB + t];
    shis[t] = g_hisJf[c * NB + t];
    __syncthreads();
    float minf = g_minJf[c], step = g_stepf[c];
    int b = blockIdx.x * blockDim.x + t;
    int s = g_off[c * (FINE + 1) + b];
    int e = g_off[c * (FINE + 1) + b + 1];
    int m = e - s;
    const float* buf = g_buf + c * HWN + s;

    double acc = 0.0;
    if (m > 0) {
        if (m <= SLAB) {
            for (int i = 0; i < m; i++) slab[i * 256 + t] = buf[i];
            for (int i = 0; i < m; i++) {
                float x = slab[i * 256 + t];
                int cnt = 0;
                for (int j = 0; j < m; j++) {
                    float y = slab[j * 256 + t];
                    cnt += (y < x) || (y == x && j < i);   // stable rank
                }
                float r = (float)(s + cnt + 1);
                int pos = 0;
                #pragma unroll
                for (int st = 128; st > 0; st >>= 1) {
                    int np = pos + st;
                    if (np <= NB && scum[np - 1] < r) pos = np;
                }
                int bi = pos > NB - 1 ? NB - 1 : pos;
                float cb = scum[bi], hb = shis[bi];
                float ratio = (r - (cb - hb)) / fmaxf(hb, 1e-12f);
                ratio = fminf(fmaxf(ratio, 0.0f), 1.0f);
                float f = minf + ((float)bi + ratio) * step;
                float d = x - f;
                acc += (double)d * (double)d;
            }
        } else {
            // rare overflow bucket (P ~ 1e-7): exact O(m^2) with global reads
            for (int i = 0; i < m; i++) {
                float x = buf[i];
                int cnt = 0;
                for (int j = 0; j < m; j++) {
                    float y = buf[j];
                    cnt += (y < x) || (y == x && j < i);
                }
                float r = (float)(s + cnt + 1);
                int pos = 0;
                for (int st = 128; st > 0; st >>= 1) {
                    int np = pos + st;
                    if (np <= NB && scum[np - 1] < r) pos = np;
                }
                int bi = pos > NB - 1 ? NB - 1 : pos;
                float cb = scum[bi], hb = shis[bi];
                float ratio = (r - (cb - hb)) / fmaxf(hb, 1e-12f);
                ratio = fminf(fmaxf(ratio, 0.0f), 1.0f);
                float f = minf + ((float)bi + ratio) * step;
                float d = x - f;
                acc += (double)d * (double)d;
            }
        }
    }

    for (int o = 16; o; o >>= 1) acc += __shfl_down_sync(0xFFFFFFFFu, acc, o);
    __shared__ double sacc[8];
    if ((t & 31) == 0) sacc[t >> 5] = acc;
    __syncthreads();
    if (t < 8) {
        double a = sacc[t];
        for (int o = 4; o; o >>= 1) a += __shfl_down_sync(0xFFu, a, o);
        if (t == 0) atomicAdd(&g_loss, a);
    }
}

// ---------------- K6: finalize --------------------------------------------------------
__global__ void k_final(float* __restrict__ out) {
    out[0] = (float)(g_loss * (100.0 / ((double)CC * (double)HWN)));
}

extern "C" void kernel_launch(void* const* d_in, const int* in_sizes, int n_in,
                              void* d_out, int out_size) {
    const float* I = (const float*)d_in[0];
    const float* J = (const float*)d_in[1];
    const int*  mI = (const int*)d_in[2];
    const int*  mJ = (const int*)d_in[3];
    float* out = (float*)d_out;

    k_init<<<(CC * FINE + 1023) / 1024, 1024>>>();

    dim3 g8((HWN / 8) / 256, CC);   // 128 x 64, 8 elems/thread
    k_pass1<<<g8, 256>>>((const float4*)I, (const float4*)J, (const int4*)mI, (const int4*)mJ);
    k_histJ<<<g8, 256>>>((const float4*)J, (const int4*)mJ);

    dim3 gs(NTILE, CC);             // 32 x 64
    k_scanA<<<gs, TILE>>>();
    k_scanB<<<CC, 256>>>();
    k_scanC<<<gs, TILE>>>();

    k_scatter<<<g8, 256>>>((const float4*)I, (const int4*)mI);

    dim3 gl(FINE / 256, CC);        // 128 x 64
    k_loss<<<gl, 256>>>();
    k_final<<<1, 1>>>(out);
}